// round 13
// baseline (speedup 1.0000x reference)
#include <cuda_runtime.h>
#include <stdint.h>

// Wavelet denoising: 3-level Haar DWT, soft-threshold with universal threshold
// (exact median of |cd1| per row), inverse DWT. Rows of L=1024, warp-per-row.
//
// Layout (cyclic float4): lane l, chunk i in [0,8) holds x[row*1024 + 128*i + 4*l .. +3].
//  - Level-1 pairs (even,odd) are adjacent inside the float4 -> intra-lane.
//  - Level-2 pairs are the two L1 outputs of the same float4 -> intra-lane.
//  - Level-3 pairs ca2[2m], ca2[2m+1] live in adjacent lanes -> one shfl.
// Median of 512 |cd1| values: interpolation bisection on float bit patterns,
// counts via register compares + __reduce_add_sync (REDUX). Exact.

__global__ __launch_bounds__(256) void wavelet_rows_kernel(
    const float* __restrict__ x, float* __restrict__ out, int nrows)
{
    const int warp = threadIdx.x >> 5;
    const int lane = threadIdx.x & 31;
    const int row  = blockIdx.x * 8 + warp;
    if (row >= nrows) return;

    const float4* __restrict__ xr = reinterpret_cast<const float4*>(x) + (size_t)row * 256;
    float4* __restrict__ outr     = reinterpret_cast<float4*>(out)     + (size_t)row * 256;

    const float C = 0.70710678118654752440f;  // 1/sqrt(2)

    // ---- load + level 1 ----
    float cd1[16], ca1[16];
#pragma unroll
    for (int i = 0; i < 8; i++) {
        float4 v = __ldcs(&xr[i * 32 + lane]);
        ca1[2*i]   = (v.x + v.y) * C;
        cd1[2*i]   = (v.x - v.y) * C;
        ca1[2*i+1] = (v.z + v.w) * C;
        cd1[2*i+1] = (v.z - v.w) * C;
    }

    // ---- level 2 (intra-lane) ----
    float ca2[8], cd2[8];
#pragma unroll
    for (int i = 0; i < 8; i++) {
        ca2[i] = (ca1[2*i] + ca1[2*i+1]) * C;
        cd2[i] = (ca1[2*i] - ca1[2*i+1]) * C;
    }

    // ---- level 3 (adjacent-lane pairs; results valid in even lanes) ----
    float ca3[8], cd3[8];
#pragma unroll
    for (int i = 0; i < 8; i++) {
        float nb = __shfl_down_sync(0xffffffffu, ca2[i], 1);
        ca3[i] = (ca2[i] + nb) * C;
        cd3[i] = (ca2[i] - nb) * C;
    }

    // ================= exact median of |cd1| (512 values, warp-wide) =================
    // s255 = 256th smallest (0-idx rank 255), s256 = rank 256; median = (s255+s256)/2.

    unsigned vmaxb = 0u;
#pragma unroll
    for (int i = 0; i < 16; i++) vmaxb = max(vmaxb, __float_as_uint(fabsf(cd1[i])));
    vmaxb = __reduce_max_sync(0xffffffffu, vmaxb);

    unsigned lo = 0u, hi = vmaxb + 1u;   // cnt(lo)=0, cnt(hi)=512  (cnt(p)=#{a<p})
    int nlo = 0, nhi = 512;
    const int R = 255;
    float s255;
    int it = 0;
    while (true) {
        if (nlo == R) {
            // exactly R values below lo -> rank-R value = min{a >= lo}
            float lof = __uint_as_float(lo);
            unsigned mb = 0x7f800000u;  // +inf
#pragma unroll
            for (int i = 0; i < 16; i++) {
                float a = fabsf(cd1[i]);
                unsigned ua = __float_as_uint(a);
                mb = (a >= lof) ? min(mb, ua) : mb;
            }
            s255 = __uint_as_float(__reduce_min_sync(0xffffffffu, mb));
            break;
        }
        if (nhi == R + 1) {
            // exactly R+1 values below hi -> rank-R value = max{a < hi}
            float hif = __uint_as_float(hi);
            unsigned mb = 0u;
#pragma unroll
            for (int i = 0; i < 16; i++) {
                float a = fabsf(cd1[i]);
                unsigned ua = __float_as_uint(a);
                mb = (a < hif) ? max(mb, ua) : mb;
            }
            s255 = __uint_as_float(__reduce_max_sync(0xffffffffu, mb));
            break;
        }
        if (hi - lo <= 1u) { s255 = __uint_as_float(lo); break; }

        unsigned span = hi - lo;
        unsigned p;
        if ((it & 3) == 3 || it > 200)
            p = lo + (span >> 1);  // midpoint safeguard -> guaranteed log-time
        else
            p = lo + (unsigned)(((unsigned long long)span * (unsigned)(R + 1 - nlo))
                                / (unsigned)(nhi - nlo));
        if (p <= lo) p = lo + 1u;
        if (p >= hi) p = hi - 1u;

        float pf = __uint_as_float(p);
        int c = 0;
#pragma unroll
        for (int i = 0; i < 16; i++) c += (fabsf(cd1[i]) < pf) ? 1 : 0;
        c = (int)__reduce_add_sync(0xffffffffu, (unsigned)c);
        if (c <= R) { lo = p; nlo = c; } else { hi = p; nhi = c; }
        it++;
    }

    // rank 256: if >=257 values <= s255 it equals s255, else min{a > s255}
    int cle = 0;
#pragma unroll
    for (int i = 0; i < 16; i++) cle += (fabsf(cd1[i]) <= s255) ? 1 : 0;
    cle = (int)__reduce_add_sync(0xffffffffu, (unsigned)cle);
    float s256;
    if (cle >= 257) {
        s256 = s255;
    } else {
        unsigned mb = 0x7f800000u;
#pragma unroll
        for (int i = 0; i < 16; i++) {
            float a = fabsf(cd1[i]);
            unsigned ua = __float_as_uint(a);
            mb = (a > s255) ? min(mb, ua) : mb;
        }
        s256 = __uint_as_float(__reduce_min_sync(0xffffffffu, mb));
    }

    float median = 0.5f * (s255 + s256);
    float lamda  = (median / 0.6745f) * 3.7232974f;   // sqrt(2*ln(1024)) as f32
    float thr1 = lamda;                                // / log2(2)
    float thr2 = lamda / 1.5849625f;                   // / log2(3)
    float thr3 = lamda * 0.5f;                         // / log2(4)

    // ---- soft thresholds ----
#pragma unroll
    for (int i = 0; i < 16; i++) {
        float a = fabsf(cd1[i]);
        cd1[i] = copysignf(fmaxf(a - thr1, 0.0f), cd1[i]);
    }
#pragma unroll
    for (int i = 0; i < 8; i++) {
        float a2 = fabsf(cd2[i]);
        cd2[i] = copysignf(fmaxf(a2 - thr2, 0.0f), cd2[i]);
        float a3 = fabsf(cd3[i]);
        cd3[i] = copysignf(fmaxf(a3 - thr3, 0.0f), cd3[i]);
    }

    // ---- inverse level 3: even lane produces (e,o); odd lane takes o from lane-1 ----
    float ca2r[8];
#pragma unroll
    for (int i = 0; i < 8; i++) {
        float e = (ca3[i] + cd3[i]) * C;
        float o = (ca3[i] - cd3[i]) * C;
        float up = __shfl_up_sync(0xffffffffu, o, 1);
        ca2r[i] = (lane & 1) ? up : e;
    }

    // ---- inverse level 2 (intra-lane) ----
    float ca1r[16];
#pragma unroll
    for (int i = 0; i < 8; i++) {
        ca1r[2*i]   = (ca2r[i] + cd2[i]) * C;
        ca1r[2*i+1] = (ca2r[i] - cd2[i]) * C;
    }

    // ---- inverse level 1 + store ----
#pragma unroll
    for (int i = 0; i < 8; i++) {
        float4 v;
        v.x = (ca1r[2*i]   + cd1[2*i])   * C;
        v.y = (ca1r[2*i]   - cd1[2*i])   * C;
        v.z = (ca1r[2*i+1] + cd1[2*i+1]) * C;
        v.w = (ca1r[2*i+1] - cd1[2*i+1]) * C;
        __stcs(&outr[i * 32 + lane], v);
    }
}

extern "C" void kernel_launch(void* const* d_in, const int* in_sizes, int n_in,
                              void* d_out, int out_size)
{
    const float* x = (const float*)d_in[0];
    float* out = (float*)d_out;
    int n = in_sizes[0];
    int nrows = n >> 10;                 // L = 1024 per row
    int blocks = (nrows + 7) / 8;        // 8 rows (warps) per 256-thread CTA
    wavelet_rows_kernel<<<blocks, 256>>>(x, out, nrows);
}

// round 14
// speedup vs baseline: 1.4411x; 1.4411x over previous
#include <cuda_runtime.h>
#include <stdint.h>

// Wavelet denoising: 3-level Haar DWT, soft-threshold (exact median of |cd1|),
// inverse DWT. Rows of L=1024, warp-per-row, cyclic float4 layout.
//
// This revision removes the 1/sqrt(2) multiplies from the transform (scales are
// folded into threshold constants and the final reconstruction FMAs), seeds the
// exact-median search with a mean-based estimate + Newton-on-CDF pivots, and
// eliminates the 64-bit division from the pivot computation. The median remains
// EXACT (terminal count==255/256 min/max passes are unchanged).

__global__ __launch_bounds__(256) void wavelet_rows_kernel(
    const float* __restrict__ x, float* __restrict__ out, int nrows)
{
    const int warp = threadIdx.x >> 5;
    const int lane = threadIdx.x & 31;
    const int row  = blockIdx.x * 8 + warp;
    if (row >= nrows) return;

    const float4* __restrict__ xr = reinterpret_cast<const float4*>(x) + (size_t)row * 256;
    float4* __restrict__ outr     = reinterpret_cast<float4*>(out)     + (size_t)row * 256;

    // ---- forward, UNNORMALIZED (plain sums/differences) ----
    // true coeffs: ca_k = C^k * ca_k',  cd_k = C^k * cd_k',  C = 1/sqrt(2)
    float cd1[16], ca1[16];
#pragma unroll
    for (int i = 0; i < 8; i++) {
        float4 v = __ldcs(&xr[i * 32 + lane]);
        ca1[2*i]   = v.x + v.y;
        cd1[2*i]   = v.x - v.y;
        ca1[2*i+1] = v.z + v.w;
        cd1[2*i+1] = v.z - v.w;
    }
    float ca2[8], cd2[8];
#pragma unroll
    for (int i = 0; i < 8; i++) {
        ca2[i] = ca1[2*i] + ca1[2*i+1];
        cd2[i] = ca1[2*i] - ca1[2*i+1];
    }
    float ca3[8], cd3[8];   // valid in even lanes
#pragma unroll
    for (int i = 0; i < 8; i++) {
        float nb = __shfl_down_sync(0xffffffffu, ca2[i], 1);
        ca3[i] = ca2[i] + nb;
        cd3[i] = ca2[i] - nb;
    }

    // ================= exact median of |cd1'| (512 values, warp-wide) =========
    // Seed: median(half-normal) ~= 0.84536 * mean(|.|). Newton pivots on the
    // empirical CDF; exact termination via count==255 / count==256 passes.
    float s = 0.f;
#pragma unroll
    for (int i = 0; i < 16; i++) s += fabsf(cd1[i]);
#pragma unroll
    for (int d = 16; d; d >>= 1) s += __shfl_xor_sync(0xffffffffu, s, d);
    const float m_est = s * 0.0016511f;          // 0.84536/512
    const float stepk = m_est * 0.0045548f;      // sigma/(512*f_med), sigma=m/0.6745

    unsigned lo = 0u, hi = 0x7f800000u;          // cnt(lo)=0, cnt(+inf)=512
    int nlo = 0, nhi = 512;
    const int R = 255;
    float s255;
    float pnewton = m_est;                       // next Newton pivot (value space)
    int it = 0;
    while (true) {
        if (nlo == R) {
            // exactly R values below lo -> rank-R value = min{a >= lo}
            unsigned mb = 0x7f800000u;
#pragma unroll
            for (int i = 0; i < 16; i++) {
                unsigned ua = __float_as_uint(cd1[i]) & 0x7fffffffu;
                if (ua >= lo) mb = min(mb, ua);
            }
            s255 = __uint_as_float(__reduce_min_sync(0xffffffffu, mb));
            break;
        }
        if (nhi == R + 1) {
            // exactly R+1 values below hi -> rank-R value = max{a < hi}
            unsigned mb = 0u;
#pragma unroll
            for (int i = 0; i < 16; i++) {
                unsigned ua = __float_as_uint(cd1[i]) & 0x7fffffffu;
                if (ua < hi) mb = max(mb, ua);
            }
            s255 = __uint_as_float(__reduce_max_sync(0xffffffffu, mb));
            break;
        }
        if (hi - lo <= 1u) { s255 = __uint_as_float(lo); break; }

        unsigned p;
        if (it < 8) p = __float_as_uint(fmaxf(pnewton, 0.0f));
        else        p = lo + ((hi - lo) >> 1);   // safeguard: bit bisection
        if (p <= lo) p = lo + 1u;
        if (p >= hi) p = hi - 1u;
        const float pf = __uint_as_float(p);

        float fc = 0.f;
#pragma unroll
        for (int i = 0; i < 16; i++) fc += (float)(fabsf(cd1[i]) < pf);
        const int c = (int)__reduce_add_sync(0xffffffffu, (unsigned)fc);
        if (c <= R) { lo = p; nlo = c; } else { hi = p; nhi = c; }
        pnewton = fmaf(255.5f - (float)c, stepk, pf);  // Newton step toward rank 255.5
        it++;
    }

    // rank 256: equals s255 if >=257 values <= s255, else min{a > s255}
    float fle = 0.f;
#pragma unroll
    for (int i = 0; i < 16; i++) fle += (float)(fabsf(cd1[i]) <= s255);
    const int cle = (int)__reduce_add_sync(0xffffffffu, (unsigned)fle);
    float s256;
    if (cle >= 257) {
        s256 = s255;
    } else {
        const unsigned sb = __float_as_uint(s255);
        unsigned mb = 0x7f800000u;
#pragma unroll
        for (int i = 0; i < 16; i++) {
            unsigned ua = __float_as_uint(cd1[i]) & 0x7fffffffu;
            if (ua > sb) mb = min(mb, ua);
        }
        s256 = __uint_as_float(__reduce_min_sync(0xffffffffu, mb));
    }

    // thresholds (true scale), then fold into primed domain
    const float median = 0.5f * (s255 + s256) * 0.70710678118654752440f;
    const float lamda  = (median / 0.6745f) * 3.7232974f;
    const float t1h = lamda * 0.70710678f;   // 0.5 * (lamda      / C)   [for s1h = 0.5*soft1']
    const float t2p = lamda * 1.26185951f;   //       (lamda/log2(3)) / C^2
    const float t3p = lamda * 1.41421356f;   //       (lamda*0.5)    / C^3

    // ---- inverse level 3 in primed domain: u = ca2r_true / C^4 ----
    float u[8];
#pragma unroll
    for (int i = 0; i < 8; i++) {
        float a3 = fabsf(cd3[i]);
        float s3 = copysignf(fmaxf(a3 - t3p, 0.0f), cd3[i]);
        float e = ca3[i] + s3;
        float o = ca3[i] - s3;
        float up = __shfl_up_sync(0xffffffffu, o, 1);
        u[i] = (lane & 1) ? up : e;
    }

    // ---- inverse level 2: v = ca1r_true / C^3 = 0.5*u +/- soft(cd2') ----
    float v[16];
#pragma unroll
    for (int i = 0; i < 8; i++) {
        float a2 = fabsf(cd2[i]);
        float s2 = copysignf(fmaxf(a2 - t2p, 0.0f), cd2[i]);
        v[2*i]   = fmaf(u[i], 0.5f,  s2);
        v[2*i+1] = fmaf(u[i], 0.5f, -s2);
    }

    // ---- inverse level 1 + store: out = 0.25*v +/- 0.5*soft(cd1') ----
#pragma unroll
    for (int i = 0; i < 8; i++) {
        float s1a = copysignf(fmaxf(fmaf(fabsf(cd1[2*i]),   0.5f, -t1h), 0.0f), cd1[2*i]);
        float s1b = copysignf(fmaxf(fmaf(fabsf(cd1[2*i+1]), 0.5f, -t1h), 0.0f), cd1[2*i+1]);
        float4 w;
        w.x = fmaf(v[2*i],   0.25f,  s1a);
        w.y = fmaf(v[2*i],   0.25f, -s1a);
        w.z = fmaf(v[2*i+1], 0.25f,  s1b);
        w.w = fmaf(v[2*i+1], 0.25f, -s1b);
        __stcs(&outr[i * 32 + lane], w);
    }
}

extern "C" void kernel_launch(void* const* d_in, const int* in_sizes, int n_in,
                              void* d_out, int out_size)
{
    const float* x = (const float*)d_in[0];
    float* out = (float*)d_out;
    int n = in_sizes[0];
    int nrows = n >> 10;                 // L = 1024 per row
    int blocks = (nrows + 7) / 8;        // 8 rows (warps) per 256-thread CTA
    wavelet_rows_kernel<<<blocks, 256>>>(x, out, nrows);
}